// round 3
// baseline (speedup 1.0000x reference)
#include <cuda_runtime.h>
#include <math.h>

// Problem constants
#define BHX 32      // B*H = 2*16
#define SEQ 2048
#define HD  64
#define FEAT_ELEMS (BHX*SEQ*HD)   // 4,194,304 floats = 16 MB each

// Scratch (device globals; allocation-free per harness rules)
__device__ __align__(128) float g_qf[FEAT_ELEMS];  // elu(q)+1, [bh][n][e]
__device__ __align__(128) float g_kf[FEAT_ELEMS];  // elu(k)+1
__device__ __align__(128) float g_rq[FEAT_ELEMS];  // rope(qf)
__device__ __align__(128) float g_rk[FEAT_ELEMS];  // rope(kf)
__device__ __align__(128) float g_v [FEAT_ELEMS];  // v
__device__ __align__(128) float g_ao[FEAT_ELEMS];  // attention output

// ---------------------------------------------------------------------------
// Kernel 1: QKV GEMM  [4096,1024] @ [1024,3072] + bias, fused elu+1 on q,k,
// fused RoPE (pairs are adjacent columns -> in-thread), scattered into
// [bh][n][64] head layout. Tile 128x128x16, 256 threads, 8x8 per thread.
// ---------------------------------------------------------------------------
__global__ __launch_bounds__(256) void qkv_gemm(const float* __restrict__ X,
                                                const float* __restrict__ W,
                                                const float* __restrict__ bias) {
    __shared__ float As[16][132];   // k-major, padded
    __shared__ float Bs[16][128];
    const int tid = threadIdx.x;
    const int bm = blockIdx.y * 128;
    const int bn = blockIdx.x * 128;
    const int tx = tid & 15, ty = tid >> 4;
    const int ar = tid >> 2,  ac = (tid & 3) * 4;
    const int br = tid >> 5,  bc = (tid & 31) * 4;

    float acc[8][8];
    #pragma unroll
    for (int i = 0; i < 8; i++)
        #pragma unroll
        for (int j = 0; j < 8; j++) acc[i][j] = 0.f;

    for (int kt = 0; kt < 1024; kt += 16) {
        #pragma unroll
        for (int l = 0; l < 2; l++) {
            int r = ar + l * 64;
            float4 v = *(const float4*)(X + (size_t)(bm + r) * 1024 + kt + ac);
            As[ac+0][r] = v.x; As[ac+1][r] = v.y; As[ac+2][r] = v.z; As[ac+3][r] = v.w;
        }
        #pragma unroll
        for (int l = 0; l < 2; l++) {
            int r = br + l * 8;
            *(float4*)(&Bs[r][bc]) = *(const float4*)(W + (size_t)(kt + r) * 3072 + bn + bc);
        }
        __syncthreads();
        #pragma unroll
        for (int k = 0; k < 16; k++) {
            float af[8], bf[8];
            *(float4*)(af)     = *(const float4*)(&As[k][ty*8]);
            *(float4*)(af + 4) = *(const float4*)(&As[k][ty*8 + 4]);
            *(float4*)(bf)     = *(const float4*)(&Bs[k][tx*8]);
            *(float4*)(bf + 4) = *(const float4*)(&Bs[k][tx*8 + 4]);
            #pragma unroll
            for (int i = 0; i < 8; i++)
                #pragma unroll
                for (int j = 0; j < 8; j++) acc[i][j] += af[i] * bf[j];
        }
        __syncthreads();
    }

    // Epilogue: bias, elu+1 (q,k), RoPE (q,k), scatter to head layout.
    // Columns owned: bn + tx*8 + j, j=0..7 -> 4 rope pairs, same for all rows.
    const int col_base = bn + tx * 8;
    const int which = col_base >> 10;      // 0=q, 1=k, 2=v
    float theta[4];
    if (which != 2) {
        #pragma unroll
        for (int p = 0; p < 4; p++) {
            int e0 = (col_base & 63) + 2 * p;     // even element index
            int pi = e0 >> 1;                      // pair index 0..31
            theta[p] = (float)(1.0 / pow(10000.0, (double)pi * (1.0 / 32.0)));
        }
    }

    #pragma unroll
    for (int i = 0; i < 8; i++) {
        int r = bm + ty * 8 + i;
        int b = r >> 11, n = r & 2047;
        #pragma unroll
        for (int p = 0; p < 4; p++) {
            int col0 = col_base + 2 * p;
            int d0 = col0 & 1023;
            int h = d0 >> 6, e0 = d0 & 63;
            int idx0 = ((b * 16 + h) * 2048 + n) * 64 + e0;
            float v0 = acc[i][2*p]   + bias[col0];
            float v1 = acc[i][2*p+1] + bias[col0 + 1];
            if (which == 2) {
                g_v[idx0]     = v0;
                g_v[idx0 + 1] = v1;
            } else {
                float f0 = (v0 > 0.f) ? (v0 + 1.f) : expf(v0);
                float f1 = (v1 > 0.f) ? (v1 + 1.f) : expf(v1);
                float s, c;
                sincosf((float)n * theta[p], &s, &c);
                float r0 = f0 * c - f1 * s;
                float r1 = f0 * s + f1 * c;
                if (which == 0) {
                    g_qf[idx0] = f0; g_qf[idx0 + 1] = f1;
                    g_rq[idx0] = r0; g_rq[idx0 + 1] = r1;
                } else {
                    g_kf[idx0] = f0; g_kf[idx0 + 1] = f1;
                    g_rk[idx0] = r0; g_rk[idx0 + 1] = r1;
                }
            }
        }
    }
}

// ---------------------------------------------------------------------------
// Kernel 2: fused attention.
// Block = (bh, 64-query tile). Streams 64-key tiles:
//   num = rq @ rk^T, den = qf @ kf^T (64x64x64), w = num/den, out += w @ v.
// smem reuse: after the num/den loop, rk/kf tiles are dead -> w aliases rk,
// v aliases kf. Total 16640 floats = 66,560 B -> 3 CTAs/SM.
// ---------------------------------------------------------------------------
__global__ __launch_bounds__(256) void attn_kernel() {
    extern __shared__ float sm[];
    float* rq_s = sm;
    float* qf_s = sm + 4160;
    float* rk_s = sm + 2 * 4160;
    float* kf_s = sm + 3 * 4160;
    float* w_s  = rk_s;            // alias: w_s[j*65 + i], live after num loop
    float* v_s  = kf_s;            // alias: v_s[j*64 + e], live after num loop
    const int tid = threadIdx.x;
    const int tx = tid & 15, ty = tid >> 4;
    const int bh = blockIdx.y;
    const int q0 = blockIdx.x * 64;

    const float* rqg = g_rq + (size_t)(bh * 2048 + q0) * 64;
    const float* qfg = g_qf + (size_t)(bh * 2048 + q0) * 64;
    #pragma unroll
    for (int l = 0; l < 4; l++) {
        int t = tid + l * 256;
        int row = t >> 4, c4 = (t & 15) * 4;
        float4 a = *(const float4*)(rqg + row * 64 + c4);
        rq_s[(c4+0)*65+row] = a.x; rq_s[(c4+1)*65+row] = a.y;
        rq_s[(c4+2)*65+row] = a.z; rq_s[(c4+3)*65+row] = a.w;
        float4 b = *(const float4*)(qfg + row * 64 + c4);
        qf_s[(c4+0)*65+row] = b.x; qf_s[(c4+1)*65+row] = b.y;
        qf_s[(c4+2)*65+row] = b.z; qf_s[(c4+3)*65+row] = b.w;
    }

    float out_acc[16];
    #pragma unroll
    for (int i = 0; i < 16; i++) out_acc[i] = 0.f;

    for (int kt = 0; kt < 32; kt++) {
        const float* rkg = g_rk + (size_t)(bh * 2048 + kt * 64) * 64;
        const float* kfg = g_kf + (size_t)(bh * 2048 + kt * 64) * 64;
        const float* vg  = g_v  + (size_t)(bh * 2048 + kt * 64) * 64;

        __syncthreads();   // previous iter's w/v reads (and iter-0 q-tile stores) done
        #pragma unroll
        for (int l = 0; l < 4; l++) {
            int t = tid + l * 256;
            int row = t >> 4, c4 = (t & 15) * 4;
            float4 a = *(const float4*)(rkg + row * 64 + c4);
            rk_s[(c4+0)*65+row] = a.x; rk_s[(c4+1)*65+row] = a.y;
            rk_s[(c4+2)*65+row] = a.z; rk_s[(c4+3)*65+row] = a.w;
            float4 b = *(const float4*)(kfg + row * 64 + c4);
            kf_s[(c4+0)*65+row] = b.x; kf_s[(c4+1)*65+row] = b.y;
            kf_s[(c4+2)*65+row] = b.z; kf_s[(c4+3)*65+row] = b.w;
        }
        __syncthreads();

        float num[16], den[16];
        #pragma unroll
        for (int i = 0; i < 16; i++) { num[i] = 0.f; den[i] = 0.f; }
        #pragma unroll 8
        for (int k = 0; k < 64; k++) {
            float ar[4], aq[4], br[4], bq[4];
            #pragma unroll
            for (int i = 0; i < 4; i++) {
                ar[i] = rq_s[k*65 + ty*4 + i];
                aq[i] = qf_s[k*65 + ty*4 + i];
            }
            #pragma unroll
            for (int j = 0; j < 4; j++) {
                br[j] = rk_s[k*65 + tx*4 + j];
                bq[j] = kf_s[k*65 + tx*4 + j];
            }
            #pragma unroll
            for (int i = 0; i < 4; i++)
                #pragma unroll
                for (int j = 0; j < 4; j++) {
                    num[i*4+j] += ar[i] * br[j];
                    den[i*4+j] += aq[i] * bq[j];
                }
        }
        __syncthreads();   // all rk/kf reads done before overwrite with w/v

        // w = num / den, stored transposed into rk region: w_s[j][i]
        #pragma unroll
        for (int i = 0; i < 4; i++)
            #pragma unroll
            for (int j = 0; j < 4; j++)
                w_s[(tx*4 + j) * 65 + ty*4 + i] = num[i*4+j] / den[i*4+j];
        // v tile into kf region
        {
            int row = tid >> 2, c4 = (tid & 3) * 16 + (tid & 3) * 0;  // 4 threads per row
        }
        #pragma unroll
        for (int l = 0; l < 4; l++) {
            int t = tid + l * 256;
            int row = t >> 4, c4 = (t & 15) * 4;
            *(float4*)(v_s + row * 64 + c4) = *(const float4*)(vg + row * 64 + c4);
        }
        __syncthreads();

        // out += w @ v
        #pragma unroll 8
        for (int j = 0; j < 64; j++) {
            float a[4], bv[4];
            #pragma unroll
            for (int i = 0; i < 4; i++) a[i] = w_s[j*65 + ty*4 + i];
            *(float4*)bv = *(const float4*)(v_s + j*64 + tx*4);
            #pragma unroll
            for (int i = 0; i < 4; i++)
                #pragma unroll
                for (int e = 0; e < 4; e++)
                    out_acc[i*4+e] += a[i] * bv[e];
        }
    }

    float* og = g_ao + (size_t)(bh * 2048 + q0) * 64;
    #pragma unroll
    for (int i = 0; i < 4; i++)
        #pragma unroll
        for (int e = 0; e < 4; e++)
            og[(ty*4 + i) * 64 + tx*4 + e] = out_acc[i*4+e];
}

// ---------------------------------------------------------------------------
// Kernel 3: output projection. A = head-gathered g_ao [4096,1024], B = w_out.
// ---------------------------------------------------------------------------
__global__ __launch_bounds__(256) void proj_gemm(const float* __restrict__ W,
                                                 const float* __restrict__ bias,
                                                 float* __restrict__ out) {
    __shared__ float As[16][132];
    __shared__ float Bs[16][128];
    const int tid = threadIdx.x;
    const int bm = blockIdx.y * 128;
    const int bn = blockIdx.x * 128;
    const int tx = tid & 15, ty = tid >> 4;
    const int ar = tid >> 2,  ac = (tid & 3) * 4;
    const int br = tid >> 5,  bc = (tid & 31) * 4;

    float acc[8][8];
    #pragma unroll
    for (int i = 0; i < 8; i++)
        #pragma unroll
        for (int j = 0; j < 8; j++) acc[i][j] = 0.f;

    for (int kt = 0; kt < 1024; kt += 16) {
        #pragma unroll
        for (int l = 0; l < 2; l++) {
            int r = bm + ar + l * 64;
            int d = kt + ac;
            int b = r >> 11, n = r & 2047;
            int h = d >> 6,  e = d & 63;
            float4 v = *(const float4*)(g_ao + (size_t)((b * 16 + h) * 2048 + n) * 64 + e);
            int rr = ar + l * 64;
            As[ac+0][rr] = v.x; As[ac+1][rr] = v.y; As[ac+2][rr] = v.z; As[ac+3][rr] = v.w;
        }
        #pragma unroll
        for (int l = 0; l < 2; l++) {
            int r = br + l * 8;
            *(float4*)(&Bs[r][bc]) = *(const float4*)(W + (size_t)(kt + r) * 1024 + bn + bc);
        }
        __syncthreads();
        #pragma unroll
        for (int k = 0; k < 16; k++) {
            float af[8], bf[8];
            *(float4*)(af)     = *(const float4*)(&As[k][ty*8]);
            *(float4*)(af + 4) = *(const float4*)(&As[k][ty*8 + 4]);
            *(float4*)(bf)     = *(const float4*)(&Bs[k][tx*8]);
            *(float4*)(bf + 4) = *(const float4*)(&Bs[k][tx*8 + 4]);
            #pragma unroll
            for (int i = 0; i < 8; i++)
                #pragma unroll
                for (int j = 0; j < 8; j++) acc[i][j] += af[i] * bf[j];
        }
        __syncthreads();
    }

    #pragma unroll
    for (int i = 0; i < 8; i++) {
        int r = bm + ty * 8 + i;
        #pragma unroll
        for (int j = 0; j < 8; j++) {
            int col = bn + tx * 8 + j;
            out[(size_t)r * 1024 + col] = acc[i][j] + bias[col];
        }
    }
}

// ---------------------------------------------------------------------------
extern "C" void kernel_launch(void* const* d_in, const int* in_sizes, int n_in,
                              void* d_out, int out_size) {
    const float* x     = (const float*)d_in[0];
    const float* w_qkv = (const float*)d_in[1];
    const float* b_qkv = (const float*)d_in[2];
    const float* w_out = (const float*)d_in[3];
    const float* b_out = (const float*)d_in[4];
    float* out = (float*)d_out;

    const int ATTN_SMEM = 16640 * 4;   // 66,560 bytes -> 3 CTAs/SM
    cudaFuncSetAttribute(attn_kernel, cudaFuncAttributeMaxDynamicSharedMemorySize, ATTN_SMEM);

    qkv_gemm<<<dim3(24, 32), 256>>>(x, w_qkv, b_qkv);
    attn_kernel<<<dim3(32, 32), 256, ATTN_SMEM>>>();
    proj_gemm<<<dim3(8, 32), 256>>>(w_out, b_out, out);
}

// round 5
// speedup vs baseline: 1.0373x; 1.0373x over previous
#include <cuda_runtime.h>
#include <math.h>

typedef unsigned long long u64;

// Packed f32x2 helpers (sm_100+): one instruction = 2 FMAs on the fma pipe.
__device__ __forceinline__ void ffma2(u64 &d, u64 a, u64 b) {
    asm("fma.rn.f32x2 %0, %1, %2, %0;" : "+l"(d) : "l"(a), "l"(b));
}
__device__ __forceinline__ u64 pack2(float lo, float hi) {
    u64 r; asm("mov.b64 %0, {%1, %2};" : "=l"(r) : "f"(lo), "f"(hi)); return r;
}
__device__ __forceinline__ void unpack2(u64 v, float &lo, float &hi) {
    asm("mov.b64 {%0, %1}, %2;" : "=f"(lo), "=f"(hi) : "l"(v));
}

// Problem constants
#define BHX 32
#define SEQ 2048
#define HD  64
#define FEAT_ELEMS (BHX*SEQ*HD)

__device__ __align__(128) float g_qf[FEAT_ELEMS];
__device__ __align__(128) float g_kf[FEAT_ELEMS];
__device__ __align__(128) float g_rq[FEAT_ELEMS];
__device__ __align__(128) float g_rk[FEAT_ELEMS];
__device__ __align__(128) float g_v [FEAT_ELEMS];
__device__ __align__(128) float g_ao[FEAT_ELEMS];

// ---------------------------------------------------------------------------
// Kernel 1: QKV GEMM + bias + elu+1 + RoPE, FFMA2 mainloop (j-paired).
// ---------------------------------------------------------------------------
__global__ __launch_bounds__(256) void qkv_gemm(const float* __restrict__ X,
                                                const float* __restrict__ W,
                                                const float* __restrict__ bias) {
    __shared__ __align__(16) float As[16][132];
    __shared__ __align__(16) float Bs[16][128];
    const int tid = threadIdx.x;
    const int bm = blockIdx.y * 128;
    const int bn = blockIdx.x * 128;
    const int tx = tid & 15, ty = tid >> 4;
    const int ar = tid >> 2,  ac = (tid & 3) * 4;
    const int br = tid >> 5,  bc = (tid & 31) * 4;

    u64 acc2[8][4];
    #pragma unroll
    for (int i = 0; i < 8; i++)
        #pragma unroll
        for (int p = 0; p < 4; p++) acc2[i][p] = 0ull;

    for (int kt = 0; kt < 1024; kt += 16) {
        #pragma unroll
        for (int l = 0; l < 2; l++) {
            int r = ar + l * 64;
            float4 v = *(const float4*)(X + (size_t)(bm + r) * 1024 + kt + ac);
            As[ac+0][r] = v.x; As[ac+1][r] = v.y; As[ac+2][r] = v.z; As[ac+3][r] = v.w;
        }
        #pragma unroll
        for (int l = 0; l < 2; l++) {
            int r = br + l * 8;
            *(float4*)(&Bs[r][bc]) = *(const float4*)(W + (size_t)(kt + r) * 3072 + bn + bc);
        }
        __syncthreads();
        #pragma unroll
        for (int k = 0; k < 16; k++) {
            float af[8];
            *(float4*)(af)     = *(const float4*)(&As[k][ty*8]);
            *(float4*)(af + 4) = *(const float4*)(&As[k][ty*8 + 4]);
            const u64* brow = (const u64*)(&Bs[k][tx*8]);
            u64 b0 = brow[0], b1 = brow[1], b2 = brow[2], b3 = brow[3];
            #pragma unroll
            for (int i = 0; i < 8; i++) {
                u64 ap = pack2(af[i], af[i]);
                ffma2(acc2[i][0], ap, b0);
                ffma2(acc2[i][1], ap, b1);
                ffma2(acc2[i][2], ap, b2);
                ffma2(acc2[i][3], ap, b3);
            }
        }
        __syncthreads();
    }

    // Epilogue: each pair p covers columns (col_base+2p, col_base+2p+1) = a RoPE pair.
    const int col_base = bn + tx * 8;
    const int which = col_base >> 10;      // 0=q, 1=k, 2=v
    float theta[4];
    if (which != 2) {
        #pragma unroll
        for (int p = 0; p < 4; p++) {
            int e0 = (col_base & 63) + 2 * p;
            int pi = e0 >> 1;
            theta[p] = (float)(1.0 / pow(10000.0, (double)pi * (1.0 / 32.0)));
        }
    }

    #pragma unroll
    for (int i = 0; i < 8; i++) {
        int r = bm + ty * 8 + i;
        int b = r >> 11, n = r & 2047;
        #pragma unroll
        for (int p = 0; p < 4; p++) {
            int col0 = col_base + 2 * p;
            int d0 = col0 & 1023;
            int h = d0 >> 6, e0 = d0 & 63;
            int idx0 = ((b * 16 + h) * 2048 + n) * 64 + e0;
            float a0, a1;
            unpack2(acc2[i][p], a0, a1);
            float v0 = a0 + bias[col0];
            float v1 = a1 + bias[col0 + 1];
            if (which == 2) {
                g_v[idx0]     = v0;
                g_v[idx0 + 1] = v1;
            } else {
                float f0 = (v0 > 0.f) ? (v0 + 1.f) : expf(v0);
                float f1 = (v1 > 0.f) ? (v1 + 1.f) : expf(v1);
                float s, c;
                sincosf((float)n * theta[p], &s, &c);
                float r0 = f0 * c - f1 * s;
                float r1 = f0 * s + f1 * c;
                if (which == 0) {
                    g_qf[idx0] = f0; g_qf[idx0 + 1] = f1;
                    g_rq[idx0] = r0; g_rq[idx0 + 1] = r1;
                } else {
                    g_kf[idx0] = f0; g_kf[idx0 + 1] = f1;
                    g_rk[idx0] = r0; g_rk[idx0 + 1] = r1;
                }
            }
        }
    }
}

// ---------------------------------------------------------------------------
// Kernel 2: fused attention with (num,den) paired FFMA2.
// smem: qp/kp = interleaved (rope, feat) f32x2 tiles, k-major, stride 66.
// After num loop kp is dead -> w_s and v_s alias its region.
// Microtile: i = ty+16r, j = tx+16c (interleaved, conflict-free LDS).
// ---------------------------------------------------------------------------
#define SQ2 66   // float2 stride for qp/kp

__global__ __launch_bounds__(256, 3) void attn_kernel() {
    extern __shared__ char smraw[];
    float2* qp = (float2*)smraw;                   // [64][66] f2 = 33792 B
    float2* kp = (float2*)(smraw + 33792);         // [64][66] f2
    float*  w_s = (float*)(smraw + 33792);         // alias kp: [j*65+i], 16640 B
    float*  v_s = (float*)(smraw + 50432);         // alias kp: [j*64+e], 16384 B
    const int tid = threadIdx.x;
    const int tx = tid & 15, ty = tid >> 4;
    const int bh = blockIdx.y;
    const int q0 = blockIdx.x * 64;

    // Load Q tiles interleaved: qp[k][i] = (rq[i][k], qf[i][k])
    const float* rqg = g_rq + (size_t)(bh * 2048 + q0) * 64;
    const float* qfg = g_qf + (size_t)(bh * 2048 + q0) * 64;
    #pragma unroll
    for (int l = 0; l < 4; l++) {
        int t = tid + l * 256;
        int row = t >> 4, c4 = (t & 15) * 4;
        float4 a = *(const float4*)(rqg + row * 64 + c4);
        float4 b = *(const float4*)(qfg + row * 64 + c4);
        qp[(c4+0)*SQ2 + row] = make_float2(a.x, b.x);
        qp[(c4+1)*SQ2 + row] = make_float2(a.y, b.y);
        qp[(c4+2)*SQ2 + row] = make_float2(a.z, b.z);
        qp[(c4+3)*SQ2 + row] = make_float2(a.w, b.w);
    }

    u64 outp[8];   // [r][half]: e pairs (2tx,2tx+1) and (2tx+32,2tx+33)
    #pragma unroll
    for (int i = 0; i < 8; i++) outp[i] = 0ull;

    for (int kt = 0; kt < 32; kt++) {
        const float* rkg = g_rk + (size_t)(bh * 2048 + kt * 64) * 64;
        const float* kfg = g_kf + (size_t)(bh * 2048 + kt * 64) * 64;
        const float* vg  = g_v  + (size_t)(bh * 2048 + kt * 64) * 64;

        __syncthreads();   // prev iter's w/v reads done (kp region free); qp stores on iter 0
        #pragma unroll
        for (int l = 0; l < 4; l++) {
            int t = tid + l * 256;
            int row = t >> 4, c4 = (t & 15) * 4;
            float4 a = *(const float4*)(rkg + row * 64 + c4);
            float4 b = *(const float4*)(kfg + row * 64 + c4);
            kp[(c4+0)*SQ2 + row] = make_float2(a.x, b.x);
            kp[(c4+1)*SQ2 + row] = make_float2(a.y, b.y);
            kp[(c4+2)*SQ2 + row] = make_float2(a.z, b.z);
            kp[(c4+3)*SQ2 + row] = make_float2(a.w, b.w);
        }
        __syncthreads();

        // num/den: one FFMA2 does num += rq*rk (lo) and den += qf*kf (hi)
        u64 acc2[16];
        #pragma unroll
        for (int i = 0; i < 16; i++) acc2[i] = 0ull;
        #pragma unroll 4
        for (int k = 0; k < 64; k++) {
            u64 a[4], b[4];
            #pragma unroll
            for (int r = 0; r < 4; r++)
                a[r] = *(const u64*)(qp + k*SQ2 + ty + 16*r);
            #pragma unroll
            for (int c = 0; c < 4; c++)
                b[c] = *(const u64*)(kp + k*SQ2 + tx + 16*c);
            #pragma unroll
            for (int r = 0; r < 4; r++)
                #pragma unroll
                for (int c = 0; c < 4; c++)
                    ffma2(acc2[r*4+c], a[r], b[c]);
        }
        __syncthreads();   // kp reads done -> region reusable for w, v

        // w = num/den into w_s (j-major); load v tile
        #pragma unroll
        for (int r = 0; r < 4; r++)
            #pragma unroll
            for (int c = 0; c < 4; c++) {
                float nu, de;
                unpack2(acc2[r*4+c], nu, de);
                w_s[(tx + 16*c) * 65 + ty + 16*r] = __fdividef(nu, de);
            }
        #pragma unroll
        for (int l = 0; l < 4; l++) {
            int t = tid + l * 256;
            int row = t >> 4, c4 = (t & 15) * 4;
            *(float4*)(v_s + row * 64 + c4) = *(const float4*)(vg + row * 64 + c4);
        }
        __syncthreads();

        // out += w @ v, e-paired FFMA2
        #pragma unroll 4
        for (int j = 0; j < 64; j++) {
            u64 wp[4];
            #pragma unroll
            for (int r = 0; r < 4; r++) {
                float wv = w_s[j*65 + ty + 16*r];
                wp[r] = pack2(wv, wv);
            }
            u64 v0 = *(const u64*)(v_s + j*64 + 2*tx);
            u64 v1 = *(const u64*)(v_s + j*64 + 2*tx + 32);
            #pragma unroll
            for (int r = 0; r < 4; r++) {
                ffma2(outp[r*2],   wp[r], v0);
                ffma2(outp[r*2+1], wp[r], v1);
            }
        }
    }

    float* og = g_ao + (size_t)(bh * 2048 + q0) * 64;
    #pragma unroll
    for (int r = 0; r < 4; r++) {
        int row = ty + 16*r;
        float lo, hi;
        unpack2(outp[r*2], lo, hi);
        *(float2*)(og + row*64 + 2*tx) = make_float2(lo, hi);
        unpack2(outp[r*2+1], lo, hi);
        *(float2*)(og + row*64 + 2*tx + 32) = make_float2(lo, hi);
    }
}

// ---------------------------------------------------------------------------
// Kernel 3: output projection (head-gathered A), FFMA2 mainloop.
// ---------------------------------------------------------------------------
__global__ __launch_bounds__(256) void proj_gemm(const float* __restrict__ W,
                                                 const float* __restrict__ bias,
                                                 float* __restrict__ out) {
    __shared__ __align__(16) float As[16][132];
    __shared__ __align__(16) float Bs[16][128];
    const int tid = threadIdx.x;
    const int bm = blockIdx.y * 128;
    const int bn = blockIdx.x * 128;
    const int tx = tid & 15, ty = tid >> 4;
    const int ar = tid >> 2,  ac = (tid & 3) * 4;
    const int br = tid >> 5,  bc = (tid & 31) * 4;

    u64 acc2[8][4];
    #pragma unroll
    for (int i = 0; i < 8; i++)
        #pragma unroll
        for (int p = 0; p < 4; p++) acc2[i][p] = 0ull;

    for (int kt = 0; kt < 1024; kt += 16) {
        #pragma unroll
        for (int l = 0; l < 2; l++) {
            int r = bm + ar + l * 64;
            int d = kt + ac;
            int b = r >> 11, n = r & 2047;
            int h = d >> 6,  e = d & 63;
            float4 v = *(const float4*)(g_ao + (size_t)((b * 16 + h) * 2048 + n) * 64 + e);
            int rr = ar + l * 64;
            As[ac+0][rr] = v.x; As[ac+1][rr] = v.y; As[ac+2][rr] = v.z; As[ac+3][rr] = v.w;
        }
        #pragma unroll
        for (int l = 0; l < 2; l++) {
            int r = br + l * 8;
            *(float4*)(&Bs[r][bc]) = *(const float4*)(W + (size_t)(kt + r) * 1024 + bn + bc);
        }
        __syncthreads();
        #pragma unroll
        for (int k = 0; k < 16; k++) {
            float af[8];
            *(float4*)(af)     = *(const float4*)(&As[k][ty*8]);
            *(float4*)(af + 4) = *(const float4*)(&As[k][ty*8 + 4]);
            const u64* brow = (const u64*)(&Bs[k][tx*8]);
            u64 b0 = brow[0], b1 = brow[1], b2 = brow[2], b3 = brow[3];
            #pragma unroll
            for (int i = 0; i < 8; i++) {
                u64 ap = pack2(af[i], af[i]);
                ffma2(acc2[i][0], ap, b0);
                ffma2(acc2[i][1], ap, b1);
                ffma2(acc2[i][2], ap, b2);
                ffma2(acc2[i][3], ap, b3);
            }
        }
        __syncthreads();
    }

    #pragma unroll
    for (int i = 0; i < 8; i++) {
        int r = bm + ty * 8 + i;
        #pragma unroll
        for (int p = 0; p < 4; p++) {
            int col0 = bn + tx * 8 + 2*p;
            float a0, a1;
            unpack2(acc2[i][p], a0, a1);
            *(float2*)(out + (size_t)r * 1024 + col0) =
                make_float2(a0 + bias[col0], a1 + bias[col0 + 1]);
        }
    }
}

// ---------------------------------------------------------------------------
extern "C" void kernel_launch(void* const* d_in, const int* in_sizes, int n_in,
                              void* d_out, int out_size) {
    const float* x     = (const float*)d_in[0];
    const float* w_qkv = (const float*)d_in[1];
    const float* b_qkv = (const float*)d_in[2];
    const float* w_out = (const float*)d_in[3];
    const float* b_out = (const float*)d_in[4];
    float* out = (float*)d_out;

    const int ATTN_SMEM = 67584;   // 2x 64x66 float2 tiles -> 3 CTAs/SM
    cudaFuncSetAttribute(attn_kernel, cudaFuncAttributeMaxDynamicSharedMemorySize, ATTN_SMEM);

    qkv_gemm<<<dim3(24, 32), 256>>>(x, w_qkv, b_qkv);
    attn_kernel<<<dim3(32, 32), 256, ATTN_SMEM>>>();
    proj_gemm<<<dim3(8, 32), 256>>>(w_out, b_out, out);
}